// round 12
// baseline (speedup 1.0000x reference)
#include <cuda_runtime.h>
#include <cuda_fp16.h>

#define B_    16384
#define T_    64
#define NB    24         // batch elems per CTA
#define CH    6          // chains per 16-lane group (6 elems, same dir)
#define NTHR  128        // 8 groups x 16 lanes; 4 warps = 1 per SMSP
#define EPADH 2056       // halves per elem tile: 64*32 + pad, 16B-aligned

typedef unsigned long long u64;

#define L2E 1.4426950408889634f

struct __align__(16) Smem {
    u64    wi[2][48][16];         // [dir][gate_row][k-pair] fp32x2
    u64    wh[2][48][8];
    __half actA[NB][EPADH];       // fp16 inter-layer activations
    __half actB[NB][EPADH];
    float  bR[2][16], bZ[2][16], bNX[2][16], bNH[2][16];
    float  wcw[4][32];
    float  wcb[4];
};

__device__ __forceinline__ u64 pack2(float lo, float hi) {
    u64 r; asm("mov.b64 %0, {%1, %2};" : "=l"(r) : "f"(lo), "f"(hi)); return r;
}
__device__ __forceinline__ void unpack2(u64 d, float& lo, float& hi) {
    asm("mov.b64 {%0, %1}, %2;" : "=f"(lo), "=f"(hi) : "l"(d));
}
__device__ __forceinline__ u64 ffma2(u64 a, u64 b, u64 c) {
    u64 d; asm("fma.rn.f32x2 %0, %1, %2, %3;" : "=l"(d) : "l"(a), "l"(b), "l"(c)); return d;
}
__device__ __forceinline__ float hadd(u64 v) {
    float lo, hi; unpack2(v, lo, hi); return lo + hi;
}
__device__ __forceinline__ u64 h2tof2(unsigned int h2) {
    float2 f = __half22float2(*reinterpret_cast<__half2*>(&h2));
    return pack2(f.x, f.y);
}
__device__ __forceinline__ float ex2(float x) {
    float r; asm("ex2.approx.ftz.f32 %0, %1;" : "=f"(r) : "f"(x)); return r;
}
__device__ __forceinline__ float rcp(float x) {
    float r; asm("rcp.approx.ftz.f32 %0, %1;" : "=f"(r) : "f"(x)); return r;
}
// s pre-scaled by log2e: sigmoid(x) = 1/(1+2^-s)
__device__ __forceinline__ float sigm2(float s) {
    return rcp(1.f + ex2(-s));
}
// s pre-scaled by 2*log2e: tanh(x) = sign * (1-2^-|s|)/(1+2^-|s|)
__device__ __forceinline__ float tanh2(float s) {
    float a = fabsf(s);
    float e = ex2(-a);
    float t = (1.f - e) * rcp(1.f + e);
    return copysignf(t, s);
}

// Stage one layer's weights into smem as f32x2 pairs, pre-scaled by log2e
// (r,z rows) / 2*log2e (n rows) so gate nonlinearities use raw ex2.
__device__ __forceinline__ void stage_layer(Smem* s,
        const float* __restrict__ Wi, const float* __restrict__ Wh,
        const float* __restrict__ bi, const float* __restrict__ bh,
        int F, int KP, int tid)
{
    for (int i = tid; i < 2 * 48 * KP; i += NTHR) {
        int d = i / (48 * KP); int r = i - d * 48 * KP;
        int row = r / KP, kp = r - row * KP;
        float sc = (row < 32) ? L2E : 2.f * L2E;
        const float* w = Wi + ((size_t)d * 48 + row) * F;
        float lo = w[2 * kp] * sc;
        float hi = (2 * kp + 1 < F) ? w[2 * kp + 1] * sc : 0.f;
        s->wi[d][row][kp] = pack2(lo, hi);
    }
    for (int i = tid; i < 2 * 48 * 8; i += NTHR) {
        int d = i / (48 * 8); int r = i - d * 48 * 8;
        int row = r >> 3, kp = r & 7;
        float sc = (row < 32) ? L2E : 2.f * L2E;
        const float* w = Wh + ((size_t)d * 48 + row) * 16;
        s->wh[d][row][kp] = pack2(w[2 * kp] * sc, w[2 * kp + 1] * sc);
    }
    for (int i = tid; i < 2 * 16; i += NTHR) {
        int d = i >> 4, uu = i & 15;
        s->bR[d][uu]  = (bi[d * 48 + uu]      + bh[d * 48 + uu])      * L2E;
        s->bZ[d][uu]  = (bi[d * 48 + 16 + uu] + bh[d * 48 + 16 + uu]) * L2E;
        s->bNX[d][uu] = bi[d * 48 + 32 + uu] * 2.f * L2E;
        s->bNH[d][uu] = bh[d * 48 + 32 + uu] * 2.f * L2E;
    }
}

// One bidirectional GRU layer. Lane u of a 16-lane group owns hidden unit u
// of CH independent chains (same dir) — weights shared across chains, so ILP
// is 6x while weight registers stay at 144. h kept in fp32 registers across
// the whole layer (recurrence unaffected by fp16); only the inter-layer tile
// is fp16. Recurrence h gathered via width-16 shfl.
template <int KP>
__device__ __forceinline__ void run_layer(Smem* s,
        const __half (*rd)[EPADH], __half (*wr)[EPADH],
        int ebase, int dir, int u)
{
    u64 wir[KP], wiz[KP], win[KP];
#pragma unroll
    for (int k = 0; k < KP; k++) {
        wir[k] = s->wi[dir][u][k];
        wiz[k] = s->wi[dir][16 + u][k];
        win[k] = s->wi[dir][32 + u][k];
    }
    u64 whr[8], whz[8], whn[8];
#pragma unroll
    for (int k = 0; k < 8; k++) {
        whr[k] = s->wh[dir][u][k];
        whz[k] = s->wh[dir][16 + u][k];
        whn[k] = s->wh[dir][32 + u][k];
    }
    const float br  = s->bR[dir][u],  bz  = s->bZ[dir][u];
    const float bnx = s->bNX[dir][u], bnh = s->bNH[dir][u];
    const int wcol = dir * 16 + u;
    const int stp  = dir ? -1 : 1;

    float h[CH];

    // x-gemm for chain c at time t: wide fp16 loads, cvt, f32x2 FMA.
    auto xgemm = [&](int c, int t, u64& ar, u64& az, u64& an) {
        ar = pack2(br, 0.f); az = pack2(bz, 0.f); an = pack2(bnx, 0.f);
        const __half* xrow = &rd[ebase + c][t * 32];
        if constexpr (KP == 2) {
            uint2 q = *(const uint2*)xrow;          // 4 halves
            u64 x0 = h2tof2(q.x);
            u64 x1 = h2tof2(q.y);
            ar = ffma2(wir[0], x0, ar); az = ffma2(wiz[0], x0, az); an = ffma2(win[0], x0, an);
            ar = ffma2(wir[1], x1, ar); az = ffma2(wiz[1], x1, az); an = ffma2(win[1], x1, an);
        } else {
            const uint4* xp = (const uint4*)xrow;   // 4 x LDS.128 = 32 halves
#pragma unroll
            for (int j = 0; j < KP / 4; j++) {
                uint4 q = xp[j];
                u64 x0 = h2tof2(q.x), x1 = h2tof2(q.y);
                u64 x2 = h2tof2(q.z), x3 = h2tof2(q.w);
                ar = ffma2(wir[4*j],   x0, ar); az = ffma2(wiz[4*j],   x0, az); an = ffma2(win[4*j],   x0, an);
                ar = ffma2(wir[4*j+1], x1, ar); az = ffma2(wiz[4*j+1], x1, az); an = ffma2(win[4*j+1], x1, an);
                ar = ffma2(wir[4*j+2], x2, ar); az = ffma2(wiz[4*j+2], x2, az); an = ffma2(win[4*j+2], x2, an);
                ar = ffma2(wir[4*j+3], x3, ar); az = ffma2(wiz[4*j+3], x3, az); an = ffma2(win[4*j+3], x3, an);
            }
        }
    };

    int t = dir ? (T_ - 1) : 0;

    // ---- peeled first step (h == 0, no recurrence) ----
#pragma unroll
    for (int c = 0; c < CH; c++) {
        u64 ar, az, an;
        xgemm(c, t, ar, az, an);
        float r = sigm2(hadd(ar));
        float z = sigm2(hadd(az));
        float n = tanh2(fmaf(r, bnh, hadd(an)));
        h[c] = fmaf(-z, n, n);                   // (1-z)*n
        wr[ebase + c][t * 32 + wcol] = __float2half_rn(h[c]);
    }
    t += stp;

#pragma unroll 1
    for (int ti = 1; ti < T_; ++ti) {
#pragma unroll
        for (int c = 0; c < CH; c++) {
            // x projection (seeded with biases)
            u64 ar, az, an;
            xgemm(c, t, ar, az, an);
            // recurrence: gather group's h via shfl, continue same accums
            u64 anh = pack2(bnh, 0.f);
#pragma unroll
            for (int k = 0; k < 4; k++) {
                float h0 = __shfl_sync(0xffffffffu, h[c], 4 * k,     16);
                float h1 = __shfl_sync(0xffffffffu, h[c], 4 * k + 1, 16);
                float h2 = __shfl_sync(0xffffffffu, h[c], 4 * k + 2, 16);
                float h3 = __shfl_sync(0xffffffffu, h[c], 4 * k + 3, 16);
                u64 hv0 = pack2(h0, h1);
                u64 hv1 = pack2(h2, h3);
                ar  = ffma2(whr[2*k],   hv0, ar);
                az  = ffma2(whz[2*k],   hv0, az);
                anh = ffma2(whn[2*k],   hv0, anh);
                ar  = ffma2(whr[2*k+1], hv1, ar);
                az  = ffma2(whz[2*k+1], hv1, az);
                anh = ffma2(whn[2*k+1], hv1, anh);
            }
            float r = sigm2(hadd(ar));
            float z = sigm2(hadd(az));
            float n = tanh2(fmaf(r, hadd(anh), hadd(an)));
            h[c] = fmaf(z, h[c] - n, n);         // (1-z)*n + z*h
            wr[ebase + c][t * 32 + wcol] = __float2half_rn(h[c]);
        }
        t += (ti == T_ - 1) ? 0 : stp;
    }
}

extern "C" __global__ void __launch_bounds__(NTHR, 1)
fused_gru(const float* __restrict__ x,
          const float* __restrict__ Wi1, const float* __restrict__ Wh1,
          const float* __restrict__ bi1, const float* __restrict__ bh1,
          const float* __restrict__ Wi5, const float* __restrict__ Wh5,
          const float* __restrict__ bi5, const float* __restrict__ bh5,
          const float* __restrict__ Wc,  const float* __restrict__ bc,
          float* __restrict__ out)
{
    extern __shared__ __align__(16) unsigned char smraw[];
    Smem* s = reinterpret_cast<Smem*>(smraw);

    const int tid   = threadIdx.x;
    const int u     = tid & 15;
    const int g     = tid >> 4;          // 8 groups; group-uniform dir
    const int dir   = g & 1;
    const int ebase = (g >> 1) * CH;     // elems ebase..ebase+5
    const int gbase = blockIdx.x * NB;

    // Stage layer-0 input x[B,T,3] into actA channels 0..3 (ch3 zeroed).
    // Tail CTA: invalid elems zero-filled (finite math; stores guarded below).
    for (int i = tid; i < NB * T_ * 4; i += NTHR) {
        int e = i >> 8; int r = i & 255; int t = r >> 2; int c = r & 3;
        float v = 0.f;
        if (c < 3 && gbase + e < B_)
            v = x[((size_t)(gbase + e)) * (T_ * 3) + t * 3 + c];
        s->actA[e][t * 32 + c] = __float2half_rn(v);
    }
    // Stage classifier weights once (unscaled).
    for (int i = tid; i < 128; i += NTHR) s->wcw[i >> 5][i & 31] = Wc[i];
    if (tid < 4) s->wcb[tid] = bc[tid];

    // Layer 0 (F=3, padded to 4 -> KP=2): actA -> actB
    stage_layer(s, Wi1, Wh1, bi1, bh1, 3, 2, tid);
    __syncthreads();
    run_layer<2>(s, s->actA, s->actB, ebase, dir, u);
    __syncthreads();

    // Layers 1..5 (F=32, KP=16), ping-pong. Final output lands in actA.
#pragma unroll 1
    for (int l = 0; l < 5; l++) {
        stage_layer(s, Wi5 + (size_t)l * 3072, Wh5 + (size_t)l * 1536,
                    bi5 + (size_t)l * 96, bh5 + (size_t)l * 96, 32, 16, tid);
        __syncthreads();
        if (l & 1) run_layer<16>(s, s->actA, s->actB, ebase, dir, u);
        else       run_layer<16>(s, s->actB, s->actA, ebase, dir, u);
        __syncthreads();
    }

    // Classifier + softmax, straight from smem to d_out (coalesced float4).
    for (int i = tid; i < NB * T_; i += NTHR) {
        int e = i / T_, t = i % T_;
        if (gbase + e >= B_) continue;
        const uint4* yp = (const uint4*)&s->actA[e][t * 32];
        const ulonglong2* w0 = (const ulonglong2*)&s->wcw[0][0];
        const ulonglong2* w1 = (const ulonglong2*)&s->wcw[1][0];
        const ulonglong2* w2 = (const ulonglong2*)&s->wcw[2][0];
        const ulonglong2* w3 = (const ulonglong2*)&s->wcw[3][0];
        u64 a0 = 0, a1 = 0, a2 = 0, a3 = 0;
#pragma unroll
        for (int j = 0; j < 4; j++) {
            uint4 q = yp[j];
            u64 y0 = h2tof2(q.x), y1 = h2tof2(q.y);
            u64 y2 = h2tof2(q.z), y3 = h2tof2(q.w);
            ulonglong2 c0 = w0[2*j], c0b = w0[2*j+1];
            ulonglong2 c1 = w1[2*j], c1b = w1[2*j+1];
            ulonglong2 c2 = w2[2*j], c2b = w2[2*j+1];
            ulonglong2 c3 = w3[2*j], c3b = w3[2*j+1];
            a0 = ffma2(c0.x, y0, a0); a0 = ffma2(c0.y, y1, a0);
            a0 = ffma2(c0b.x, y2, a0); a0 = ffma2(c0b.y, y3, a0);
            a1 = ffma2(c1.x, y0, a1); a1 = ffma2(c1.y, y1, a1);
            a1 = ffma2(c1b.x, y2, a1); a1 = ffma2(c1b.y, y3, a1);
            a2 = ffma2(c2.x, y0, a2); a2 = ffma2(c2.y, y1, a2);
            a2 = ffma2(c2b.x, y2, a2); a2 = ffma2(c2b.y, y3, a2);
            a3 = ffma2(c3.x, y0, a3); a3 = ffma2(c3.y, y1, a3);
            a3 = ffma2(c3b.x, y2, a3); a3 = ffma2(c3b.y, y3, a3);
        }
        float l0 = hadd(a0) + s->wcb[0];
        float l1 = hadd(a1) + s->wcb[1];
        float l2 = hadd(a2) + s->wcb[2];
        float l3 = hadd(a3) + s->wcb[3];
        float m  = fmaxf(fmaxf(l0, l1), fmaxf(l2, l3));
        float e0 = __expf(l0 - m), e1 = __expf(l1 - m);
        float e2 = __expf(l2 - m), e3 = __expf(l3 - m);
        float rs = __fdividef(1.f, e0 + e1 + e2 + e3);
        float4 o = make_float4(e0 * rs, e1 * rs, e2 * rs, e3 * rs);
        reinterpret_cast<float4*>(out)[((size_t)(gbase + e)) * T_ + t] = o;
    }
}

extern "C" void kernel_launch(void* const* d_in, const int* in_sizes, int n_in,
                              void* d_out, int out_size)
{
    const float* x   = (const float*)d_in[0];
    const float* Wi1 = (const float*)d_in[1];
    const float* Wh1 = (const float*)d_in[2];
    const float* bi1 = (const float*)d_in[3];
    const float* bh1 = (const float*)d_in[4];
    const float* Wi5 = (const float*)d_in[5];
    const float* Wh5 = (const float*)d_in[6];
    const float* bi5 = (const float*)d_in[7];
    const float* bh5 = (const float*)d_in[8];
    const float* Wc  = (const float*)d_in[9];
    const float* bc  = (const float*)d_in[10];
    float* out = (float*)d_out;

    static bool once = []() {
        cudaFuncSetAttribute(fused_gru,
            cudaFuncAttributeMaxDynamicSharedMemorySize, (int)sizeof(Smem));
        return true;
    }();
    (void)once;

    fused_gru<<<(B_ + NB - 1) / NB, NTHR, sizeof(Smem)>>>(
        x, Wi1, Wh1, bi1, bh1, Wi5, Wh5, bi5, bh5, Wc, bc, out);
}

// round 13
// speedup vs baseline: 1.1160x; 1.1160x over previous
#include <cuda_runtime.h>

#define B_    16384
#define T_    64
#define NB    12         // batch elems per CTA
#define CH    3          // chains per 32-lane warp-group
#define NTHR  256        // 8 warps; warp = one (3-chain, dir) group; 2 warps/SMSP
#define EPAD  2052       // floats per elem tile: 64*32 + pad, 16B-aligned

typedef unsigned long long u64;

#define L2E 1.4426950408889634f

struct __align__(16) Smem {
    u64   wi[2][48][16];          // [dir][gate_row][k-pair] f32x2
    u64   wh[2][48][8];
    float actA[NB][EPAD];
    float actB[NB][EPAD];
    float bR[2][16], bZ[2][16], bNX[2][16], bNH[2][16];
    float wcw[4][32];
    float wcb[4];
};

__device__ __forceinline__ u64 pack2(float lo, float hi) {
    u64 r; asm("mov.b64 %0, {%1, %2};" : "=l"(r) : "f"(lo), "f"(hi)); return r;
}
__device__ __forceinline__ void unpack2(u64 d, float& lo, float& hi) {
    asm("mov.b64 {%0, %1}, %2;" : "=f"(lo), "=f"(hi) : "l"(d));
}
__device__ __forceinline__ u64 ffma2(u64 a, u64 b, u64 c) {
    u64 d; asm("fma.rn.f32x2 %0, %1, %2, %3;" : "=l"(d) : "l"(a), "l"(b), "l"(c)); return d;
}
__device__ __forceinline__ float hadd(u64 v) {
    float lo, hi; unpack2(v, lo, hi); return lo + hi;
}
__device__ __forceinline__ float ex2(float x) {
    float r; asm("ex2.approx.ftz.f32 %0, %1;" : "=f"(r) : "f"(x)); return r;
}
__device__ __forceinline__ float rcp(float x) {
    float r; asm("rcp.approx.ftz.f32 %0, %1;" : "=f"(r) : "f"(x)); return r;
}
// s pre-scaled by log2e: sigmoid(x) = 1/(1+2^-s)
__device__ __forceinline__ float sigm2(float s) {
    return rcp(1.f + ex2(-s));
}
// s pre-scaled by 2*log2e: tanh(x) = sign * (1-2^-|s|)/(1+2^-|s|)
__device__ __forceinline__ float tanh2(float s) {
    float a = fabsf(s);
    float e = ex2(-a);
    float t = (1.f - e) * rcp(1.f + e);
    return copysignf(t, s);
}

// Stage one layer's weights into smem as f32x2 pairs, pre-scaled by log2e
// (r,z rows) / 2*log2e (n rows) so gate nonlinearities use raw ex2.
__device__ __forceinline__ void stage_layer(Smem* s,
        const float* __restrict__ Wi, const float* __restrict__ Wh,
        const float* __restrict__ bi, const float* __restrict__ bh,
        int F, int KP, int tid)
{
    for (int i = tid; i < 2 * 48 * KP; i += NTHR) {
        int d = i / (48 * KP); int r = i - d * 48 * KP;
        int row = r / KP, kp = r - row * KP;
        float sc = (row < 32) ? L2E : 2.f * L2E;
        const float* w = Wi + ((size_t)d * 48 + row) * F;
        float lo = w[2 * kp] * sc;
        float hi = (2 * kp + 1 < F) ? w[2 * kp + 1] * sc : 0.f;
        s->wi[d][row][kp] = pack2(lo, hi);
    }
    for (int i = tid; i < 2 * 48 * 8; i += NTHR) {
        int d = i / (48 * 8); int r = i - d * 48 * 8;
        int row = r >> 3, kp = r & 7;
        float sc = (row < 32) ? L2E : 2.f * L2E;
        const float* w = Wh + ((size_t)d * 48 + row) * 16;
        s->wh[d][row][kp] = pack2(w[2 * kp] * sc, w[2 * kp + 1] * sc);
    }
    for (int i = tid; i < 2 * 16; i += NTHR) {
        int d = i >> 4, uu = i & 15;
        s->bR[d][uu]  = (bi[d * 48 + uu]      + bh[d * 48 + uu])      * L2E;
        s->bZ[d][uu]  = (bi[d * 48 + 16 + uu] + bh[d * 48 + 16 + uu]) * L2E;
        s->bNX[d][uu] = bi[d * 48 + 32 + uu] * 2.f * L2E;
        s->bNH[d][uu] = bh[d * 48 + 32 + uu] * 2.f * L2E;
    }
}

// One bidirectional GRU layer, K-split across warp halves: lane (u, half)
// owns unit u's k-half of CH=3 chains. Per-lane weight registers halved (72)
// so TWO warps fit per SMSP and interleave through each other's gate stalls.
// Partials combined with one shfl_xor(16) per gate; gates computed (validly)
// in both halves. Recurrence h gathered via width-32 shfl from lanes 0..15.
template <int KPH>
__device__ __forceinline__ void run_layer(Smem* s,
        const float (*rd)[EPAD], float (*wr)[EPAD],
        int ebase, int dir, int u, int half)
{
    u64 wir[KPH], wiz[KPH], win[KPH];
#pragma unroll
    for (int k = 0; k < KPH; k++) {
        wir[k] = s->wi[dir][u][half * KPH + k];
        wiz[k] = s->wi[dir][16 + u][half * KPH + k];
        win[k] = s->wi[dir][32 + u][half * KPH + k];
    }
    u64 whr[4], whz[4], whn[4];
#pragma unroll
    for (int k = 0; k < 4; k++) {
        whr[k] = s->wh[dir][u][half * 4 + k];
        whz[k] = s->wh[dir][16 + u][half * 4 + k];
        whn[k] = s->wh[dir][32 + u][half * 4 + k];
    }
    // biases seeded in half 0 only (reduction would double-count otherwise)
    const float br  = half ? 0.f : s->bR[dir][u];
    const float bz  = half ? 0.f : s->bZ[dir][u];
    const float bnx = half ? 0.f : s->bNX[dir][u];
    const float bnh0= half ? 0.f : s->bNH[dir][u];
    const float bnh = s->bNH[dir][u];      // scalar form (no reduction path)
    const int wcol = dir * 16 + u;
    const int stp  = dir ? -1 : 1;

    float h[CH];

    // x-projection partial for chain c at time t (this lane's k-half)
    auto xgemm = [&](int c, int t, u64& ar, u64& az, u64& an) {
        ar = pack2(br, 0.f); az = pack2(bz, 0.f); an = pack2(bnx, 0.f);
        const u64* xp = (const u64*)&rd[ebase + c][t * 32] + half * KPH;
#pragma unroll
        for (int k = 0; k < KPH; k++) {
            u64 xv = xp[k];
            ar = ffma2(wir[k], xv, ar);
            az = ffma2(wiz[k], xv, az);
            an = ffma2(win[k], xv, an);
        }
    };

    int t = dir ? (T_ - 1) : 0;

    // ---- peeled first step (h == 0, no recurrence) ----
#pragma unroll
    for (int c = 0; c < CH; c++) {
        u64 ar, az, an;
        xgemm(c, t, ar, az, an);
        float arf = hadd(ar);  arf += __shfl_xor_sync(0xffffffffu, arf, 16);
        float azf = hadd(az);  azf += __shfl_xor_sync(0xffffffffu, azf, 16);
        float anf = hadd(an);  anf += __shfl_xor_sync(0xffffffffu, anf, 16);
        float r = sigm2(arf);
        float z = sigm2(azf);
        float n = tanh2(fmaf(r, bnh, anf));
        h[c] = fmaf(-z, n, n);                   // (1-z)*n
        if (half == 0) wr[ebase + c][t * 32 + wcol] = h[c];
    }
    t += stp;

#pragma unroll 1
    for (int ti = 1; ti < T_; ++ti) {
#pragma unroll
        for (int c = 0; c < CH; c++) {
            u64 ar, az, an;
            xgemm(c, t, ar, az, an);
            // recurrence partial: gather h (valid in all lanes) from lanes 0-15
            u64 anh = pack2(bnh0, 0.f);
#pragma unroll
            for (int k = 0; k < 4; k++) {
                int ub = half * 8 + 2 * k;       // this half covers units ub, ub+1
                float h0 = __shfl_sync(0xffffffffu, h[c], ub,     32);
                float h1 = __shfl_sync(0xffffffffu, h[c], ub + 1, 32);
                u64 hv = pack2(h0, h1);
                ar  = ffma2(whr[k], hv, ar);
                az  = ffma2(whz[k], hv, az);
                anh = ffma2(whn[k], hv, anh);
            }
            float arf  = hadd(ar);   arf  += __shfl_xor_sync(0xffffffffu, arf, 16);
            float azf  = hadd(az);   azf  += __shfl_xor_sync(0xffffffffu, azf, 16);
            float anxf = hadd(an);   anxf += __shfl_xor_sync(0xffffffffu, anxf, 16);
            float anhf = hadd(anh);  anhf += __shfl_xor_sync(0xffffffffu, anhf, 16);
            float r = sigm2(arf);
            float z = sigm2(azf);
            float n = tanh2(fmaf(r, anhf, anxf));
            h[c] = fmaf(z, h[c] - n, n);         // (1-z)*n + z*h
            if (half == 0) wr[ebase + c][t * 32 + wcol] = h[c];
        }
        t += (ti == T_ - 1) ? 0 : stp;
    }
}

extern "C" __global__ void __launch_bounds__(NTHR, 1)
fused_gru(const float* __restrict__ x,
          const float* __restrict__ Wi1, const float* __restrict__ Wh1,
          const float* __restrict__ bi1, const float* __restrict__ bh1,
          const float* __restrict__ Wi5, const float* __restrict__ Wh5,
          const float* __restrict__ bi5, const float* __restrict__ bh5,
          const float* __restrict__ Wc,  const float* __restrict__ bc,
          float* __restrict__ out)
{
    extern __shared__ __align__(16) unsigned char smraw[];
    Smem* s = reinterpret_cast<Smem*>(smraw);

    const int tid   = threadIdx.x;
    const int lane  = tid & 31;
    const int u     = lane & 15;
    const int half  = lane >> 4;
    const int w     = tid >> 5;          // 8 warps; warp-uniform dir
    const int dir   = w & 1;
    const int ebase = (w >> 1) * CH;     // elems ebase..ebase+2
    const int gbase = blockIdx.x * NB;

    // Stage layer-0 input x[B,T,3] into actA channels 0..3 (ch3 zeroed).
    // Tail CTA: invalid elems zero-filled (finite math; stores guarded below).
    for (int i = tid; i < NB * T_ * 4; i += NTHR) {
        int e = i >> 8; int r = i & 255; int t = r >> 2; int c = r & 3;
        float v = 0.f;
        if (c < 3 && gbase + e < B_)
            v = x[((size_t)(gbase + e)) * (T_ * 3) + t * 3 + c];
        s->actA[e][t * 32 + c] = v;
    }
    // Stage classifier weights once (unscaled).
    for (int i = tid; i < 128; i += NTHR) s->wcw[i >> 5][i & 31] = Wc[i];
    if (tid < 4) s->wcb[tid] = bc[tid];

    // Layer 0 (F=3, padded to 4 -> 2 k-pairs, 1 per half): actA -> actB
    stage_layer(s, Wi1, Wh1, bi1, bh1, 3, 2, tid);
    __syncthreads();
    run_layer<1>(s, s->actA, s->actB, ebase, dir, u, half);
    __syncthreads();

    // Layers 1..5 (F=32 -> 16 k-pairs, 8 per half), ping-pong -> ends in actA.
#pragma unroll 1
    for (int l = 0; l < 5; l++) {
        stage_layer(s, Wi5 + (size_t)l * 3072, Wh5 + (size_t)l * 1536,
                    bi5 + (size_t)l * 96, bh5 + (size_t)l * 96, 32, 16, tid);
        __syncthreads();
        if (l & 1) run_layer<8>(s, s->actA, s->actB, ebase, dir, u, half);
        else       run_layer<8>(s, s->actB, s->actA, ebase, dir, u, half);
        __syncthreads();
    }

    // Classifier + softmax, straight from smem to d_out (coalesced float4).
    for (int i = tid; i < NB * T_; i += NTHR) {
        int e = i >> 6, t = i & 63;
        if (gbase + e >= B_) continue;
        const ulonglong2* yp = (const ulonglong2*)&s->actA[e][t * 32];
        const ulonglong2* w0 = (const ulonglong2*)&s->wcw[0][0];
        const ulonglong2* w1 = (const ulonglong2*)&s->wcw[1][0];
        const ulonglong2* w2 = (const ulonglong2*)&s->wcw[2][0];
        const ulonglong2* w3 = (const ulonglong2*)&s->wcw[3][0];
        u64 a0 = 0, a1 = 0, a2 = 0, a3 = 0;
#pragma unroll
        for (int k = 0; k < 8; k++) {
            ulonglong2 yv = yp[k];
            ulonglong2 c0 = w0[k], c1 = w1[k], c2 = w2[k], c3 = w3[k];
            a0 = ffma2(c0.x, yv.x, a0); a0 = ffma2(c0.y, yv.y, a0);
            a1 = ffma2(c1.x, yv.x, a1); a1 = ffma2(c1.y, yv.y, a1);
            a2 = ffma2(c2.x, yv.x, a2); a2 = ffma2(c2.y, yv.y, a2);
            a3 = ffma2(c3.x, yv.x, a3); a3 = ffma2(c3.y, yv.y, a3);
        }
        float l0 = hadd(a0) + s->wcb[0];
        float l1 = hadd(a1) + s->wcb[1];
        float l2 = hadd(a2) + s->wcb[2];
        float l3 = hadd(a3) + s->wcb[3];
        float m  = fmaxf(fmaxf(l0, l1), fmaxf(l2, l3));
        float e0 = __expf(l0 - m), e1 = __expf(l1 - m);
        float e2 = __expf(l2 - m), e3 = __expf(l3 - m);
        float rs = __fdividef(1.f, e0 + e1 + e2 + e3);
        float4 o = make_float4(e0 * rs, e1 * rs, e2 * rs, e3 * rs);
        reinterpret_cast<float4*>(out)[((size_t)(gbase + e)) * T_ + t] = o;
    }
}

extern "C" void kernel_launch(void* const* d_in, const int* in_sizes, int n_in,
                              void* d_out, int out_size)
{
    const float* x   = (const float*)d_in[0];
    const float* Wi1 = (const float*)d_in[1];
    const float* Wh1 = (const float*)d_in[2];
    const float* bi1 = (const float*)d_in[3];
    const float* bh1 = (const float*)d_in[4];
    const float* Wi5 = (const float*)d_in[5];
    const float* Wh5 = (const float*)d_in[6];
    const float* bi5 = (const float*)d_in[7];
    const float* bh5 = (const float*)d_in[8];
    const float* Wc  = (const float*)d_in[9];
    const float* bc  = (const float*)d_in[10];
    float* out = (float*)d_out;

    static bool once = []() {
        cudaFuncSetAttribute(fused_gru,
            cudaFuncAttributeMaxDynamicSharedMemorySize, (int)sizeof(Smem));
        return true;
    }();
    (void)once;

    fused_gru<<<(B_ + NB - 1) / NB, NTHR, sizeof(Smem)>>>(
        x, Wi1, Wh1, bi1, bh1, Wi5, Wh5, bi5, bh5, Wc, bc, out);
}

// round 14
// speedup vs baseline: 1.2953x; 1.1606x over previous
#include <cuda_runtime.h>

#define B_    16384
#define T_    64
#define NB    12         // batch elems per CTA
#define CH    3          // chains per 16-lane group (3 elems, same dir)
#define NTHR  128        // 8 groups x 16 lanes; 4 warps = 1 per SMSP
#define EPAD  2052       // floats per elem tile: 64*32 + pad, 16B-aligned

typedef unsigned long long u64;

#define L2E 1.4426950408889634f

struct __align__(16) Smem {
    u64   wi[2][48][16];          // [dir][gate_row][k-pair] f32x2
    u64   wh[2][48][8];
    float actA[NB][EPAD];
    float actB[NB][EPAD];
    float bR[2][16], bZ[2][16], bNX[2][16], bNH[2][16];
    float wcw[4][32];
    float wcb[4];
};

__device__ __forceinline__ u64 pack2(float lo, float hi) {
    u64 r; asm("mov.b64 %0, {%1, %2};" : "=l"(r) : "f"(lo), "f"(hi)); return r;
}
__device__ __forceinline__ void unpack2(u64 d, float& lo, float& hi) {
    asm("mov.b64 {%0, %1}, %2;" : "=f"(lo), "=f"(hi) : "l"(d));
}
__device__ __forceinline__ u64 ffma2(u64 a, u64 b, u64 c) {
    u64 d; asm("fma.rn.f32x2 %0, %1, %2, %3;" : "=l"(d) : "l"(a), "l"(b), "l"(c)); return d;
}
__device__ __forceinline__ float hadd(u64 v) {
    float lo, hi; unpack2(v, lo, hi); return lo + hi;
}
__device__ __forceinline__ float ex2(float x) {
    float r; asm("ex2.approx.ftz.f32 %0, %1;" : "=f"(r) : "f"(x)); return r;
}
__device__ __forceinline__ float rcp(float x) {
    float r; asm("rcp.approx.ftz.f32 %0, %1;" : "=f"(r) : "f"(x)); return r;
}
// s pre-scaled by log2e: sigmoid(x) = 1/(1+2^-s)
__device__ __forceinline__ float sigm2(float s) {
    return rcp(1.f + ex2(-s));
}
// s pre-scaled by 2*log2e: tanh(x) = sign * (1-2^-|s|)/(1+2^-|s|)
__device__ __forceinline__ float tanh2(float s) {
    float a = fabsf(s);
    float e = ex2(-a);
    float t = (1.f - e) * rcp(1.f + e);
    return copysignf(t, s);
}

// Stage one layer's weights into smem as f32x2 pairs, pre-scaled by log2e
// (r,z rows) / 2*log2e (n rows) so gate nonlinearities use raw ex2.
__device__ __forceinline__ void stage_layer(Smem* s,
        const float* __restrict__ Wi, const float* __restrict__ Wh,
        const float* __restrict__ bi, const float* __restrict__ bh,
        int F, int KP, int tid)
{
    for (int i = tid; i < 2 * 48 * KP; i += NTHR) {
        int d = i / (48 * KP); int r = i - d * 48 * KP;
        int row = r / KP, kp = r - row * KP;
        float sc = (row < 32) ? L2E : 2.f * L2E;
        const float* w = Wi + ((size_t)d * 48 + row) * F;
        float lo = w[2 * kp] * sc;
        float hi = (2 * kp + 1 < F) ? w[2 * kp + 1] * sc : 0.f;
        s->wi[d][row][kp] = pack2(lo, hi);
    }
    for (int i = tid; i < 2 * 48 * 8; i += NTHR) {
        int d = i / (48 * 8); int r = i - d * 48 * 8;
        int row = r >> 3, kp = r & 7;
        float sc = (row < 32) ? L2E : 2.f * L2E;
        const float* w = Wh + ((size_t)d * 48 + row) * 16;
        s->wh[d][row][kp] = pack2(w[2 * kp] * sc, w[2 * kp + 1] * sc);
    }
    for (int i = tid; i < 2 * 16; i += NTHR) {
        int d = i >> 4, uu = i & 15;
        s->bR[d][uu]  = (bi[d * 48 + uu]      + bh[d * 48 + uu])      * L2E;
        s->bZ[d][uu]  = (bi[d * 48 + 16 + uu] + bh[d * 48 + 16 + uu]) * L2E;
        s->bNX[d][uu] = bi[d * 48 + 32 + uu] * 2.f * L2E;
        s->bNH[d][uu] = bh[d * 48 + 32 + uu] * 2.f * L2E;
    }
}

// One bidirectional GRU layer. Lane u of a 16-lane group owns hidden unit u
// of CH independent chains (3 batch elems, same dir). Weights shared across
// chains and held in registers. Recurrence: h re-read from the output tile
// as 4 broadcast LDS.128 per chain (h was stored there last step) — replaces
// the 16-shfl + 8-pack gather, cutting MIO ops ~2x and issue slots ~25%.
template <int KP>
__device__ __forceinline__ void run_layer(Smem* s,
        const float (*rd)[EPAD], float (*wr)[EPAD],
        int ebase, int dir, int u)
{
    u64 wir[KP], wiz[KP], win[KP];
#pragma unroll
    for (int k = 0; k < KP; k++) {
        wir[k] = s->wi[dir][u][k];
        wiz[k] = s->wi[dir][16 + u][k];
        win[k] = s->wi[dir][32 + u][k];
    }
    u64 whr[8], whz[8], whn[8];
#pragma unroll
    for (int k = 0; k < 8; k++) {
        whr[k] = s->wh[dir][u][k];
        whz[k] = s->wh[dir][16 + u][k];
        whn[k] = s->wh[dir][32 + u][k];
    }
    const float br  = s->bR[dir][u],  bz  = s->bZ[dir][u];
    const float bnx = s->bNX[dir][u], bnh = s->bNH[dir][u];
    const int wcol = dir * 16 + u;
    const int stp  = dir ? -1 : 1;

    float h[CH];

    // x-gemm for chain c at time t (biases folded into accumulator init)
    auto xgemm = [&](int c, int t, u64& ar, u64& az, u64& an) {
        ar = pack2(br, 0.f); az = pack2(bz, 0.f); an = pack2(bnx, 0.f);
        const ulonglong2* xp = (const ulonglong2*)&rd[ebase + c][t * 32];
#pragma unroll
        for (int k = 0; k < KP / 2; k++) {
            ulonglong2 xv = xp[k];
            ar = ffma2(wir[2*k],   xv.x, ar);
            az = ffma2(wiz[2*k],   xv.x, az);
            an = ffma2(win[2*k],   xv.x, an);
            ar = ffma2(wir[2*k+1], xv.y, ar);
            az = ffma2(wiz[2*k+1], xv.y, az);
            an = ffma2(win[2*k+1], xv.y, an);
        }
    };

    int t = dir ? (T_ - 1) : 0;

    // ---- peeled first step (h == 0, no recurrence) ----
#pragma unroll
    for (int c = 0; c < CH; c++) {
        u64 ar, az, an;
        xgemm(c, t, ar, az, an);
        float r = sigm2(hadd(ar));
        float z = sigm2(hadd(az));
        float n = tanh2(fmaf(r, bnh, hadd(an)));
        h[c] = fmaf(-z, n, n);                   // (1-z)*n
        wr[ebase + c][t * 32 + wcol] = h[c];
    }
    __syncwarp();
    int prev_t = t;
    t += stp;

#pragma unroll 1
    for (int ti = 1; ti < T_; ++ti) {
        // issue all chains' h-vector loads first (latency hidden by xgemms)
        ulonglong2 hA[CH], hB[CH];
#pragma unroll
        for (int c = 0; c < CH; c++) {
            const ulonglong2* hp =
                (const ulonglong2*)&wr[ebase + c][prev_t * 32 + dir * 16];
            hA[c] = hp[0];
            hB[c] = hp[1];
        }
        // x projections (independent FMA work under the LDS latency)
        u64 xar[CH], xaz[CH], xan[CH];
#pragma unroll
        for (int c = 0; c < CH; c++) xgemm(c, t, xar[c], xaz[c], xan[c]);

        // recurrent gemm + gates per chain (chains interleave through MUFU)
#pragma unroll
        for (int c = 0; c < CH; c++) {
            u64 ar = xar[c], az = xaz[c], anh = pack2(bnh, 0.f);
            u64 hv0 = hA[c].x, hv1 = hA[c].y, hv2 = hB[c].x, hv3 = hB[c].y;
            ar  = ffma2(whr[0], hv0, ar);
            az  = ffma2(whz[0], hv0, az);
            anh = ffma2(whn[0], hv0, anh);
            ar  = ffma2(whr[1], hv1, ar);
            az  = ffma2(whz[1], hv1, az);
            anh = ffma2(whn[1], hv1, anh);
            ar  = ffma2(whr[2], hv2, ar);
            az  = ffma2(whz[2], hv2, az);
            anh = ffma2(whn[2], hv2, anh);
            ar  = ffma2(whr[3], hv3, ar);
            az  = ffma2(whz[3], hv3, az);
            anh = ffma2(whn[3], hv3, anh);
            const ulonglong2* hp =
                (const ulonglong2*)&wr[ebase + c][prev_t * 32 + dir * 16];
            ulonglong2 hC = hp[2], hD = hp[3];
            u64 hv4 = hC.x, hv5 = hC.y, hv6 = hD.x, hv7 = hD.y;
            ar  = ffma2(whr[4], hv4, ar);
            az  = ffma2(whz[4], hv4, az);
            anh = ffma2(whn[4], hv4, anh);
            ar  = ffma2(whr[5], hv5, ar);
            az  = ffma2(whz[5], hv5, az);
            anh = ffma2(whn[5], hv5, anh);
            ar  = ffma2(whr[6], hv6, ar);
            az  = ffma2(whz[6], hv6, az);
            anh = ffma2(whn[6], hv6, anh);
            ar  = ffma2(whr[7], hv7, ar);
            az  = ffma2(whz[7], hv7, az);
            anh = ffma2(whn[7], hv7, anh);

            float r = sigm2(hadd(ar));
            float z = sigm2(hadd(az));
            float n = tanh2(fmaf(r, hadd(anh), hadd(xan[c])));
            h[c] = fmaf(z, h[c] - n, n);         // (1-z)*n + z*h
            wr[ebase + c][t * 32 + wcol] = h[c];
        }
        __syncwarp();
        prev_t = t;
        t += (ti == T_ - 1) ? 0 : stp;
    }
}

extern "C" __global__ void __launch_bounds__(NTHR, 1)
fused_gru(const float* __restrict__ x,
          const float* __restrict__ Wi1, const float* __restrict__ Wh1,
          const float* __restrict__ bi1, const float* __restrict__ bh1,
          const float* __restrict__ Wi5, const float* __restrict__ Wh5,
          const float* __restrict__ bi5, const float* __restrict__ bh5,
          const float* __restrict__ Wc,  const float* __restrict__ bc,
          float* __restrict__ out)
{
    extern __shared__ __align__(16) unsigned char smraw[];
    Smem* s = reinterpret_cast<Smem*>(smraw);

    const int tid   = threadIdx.x;
    const int u     = tid & 15;
    const int g     = tid >> 4;          // 8 groups; group-uniform dir
    const int dir   = g & 1;
    const int ebase = (g >> 1) * CH;     // elems ebase..ebase+2
    const int gbase = blockIdx.x * NB;

    // Stage layer-0 input x[B,T,3] into actA channels 0..3 (ch3 zeroed).
    // Tail CTA: invalid elems zero-filled (finite math; stores guarded below).
    for (int i = tid; i < NB * T_ * 4; i += NTHR) {
        int e = i >> 8; int r = i & 255; int t = r >> 2; int c = r & 3;
        float v = 0.f;
        if (c < 3 && gbase + e < B_)
            v = x[((size_t)(gbase + e)) * (T_ * 3) + t * 3 + c];
        s->actA[e][t * 32 + c] = v;
    }
    // Stage classifier weights once (unscaled).
    for (int i = tid; i < 128; i += NTHR) s->wcw[i >> 5][i & 31] = Wc[i];
    if (tid < 4) s->wcb[tid] = bc[tid];

    // Layer 0 (F=3, padded to 4 -> KP=2): actA -> actB
    stage_layer(s, Wi1, Wh1, bi1, bh1, 3, 2, tid);
    __syncthreads();
    run_layer<2>(s, s->actA, s->actB, ebase, dir, u);
    __syncthreads();

    // Layers 1..5 (F=32, KP=16), ping-pong. Final output lands in actA.
#pragma unroll 1
    for (int l = 0; l < 5; l++) {
        stage_layer(s, Wi5 + (size_t)l * 3072, Wh5 + (size_t)l * 1536,
                    bi5 + (size_t)l * 96, bh5 + (size_t)l * 96, 32, 16, tid);
        __syncthreads();
        if (l & 1) run_layer<16>(s, s->actA, s->actB, ebase, dir, u);
        else       run_layer<16>(s, s->actB, s->actA, ebase, dir, u);
        __syncthreads();
    }

    // Classifier + softmax, straight from smem to d_out (coalesced float4).
    for (int i = tid; i < NB * T_; i += NTHR) {
        int e = i >> 6, t = i & 63;
        if (gbase + e >= B_) continue;
        const ulonglong2* yp = (const ulonglong2*)&s->actA[e][t * 32];
        const ulonglong2* w0 = (const ulonglong2*)&s->wcw[0][0];
        const ulonglong2* w1 = (const ulonglong2*)&s->wcw[1][0];
        const ulonglong2* w2 = (const ulonglong2*)&s->wcw[2][0];
        const ulonglong2* w3 = (const ulonglong2*)&s->wcw[3][0];
        u64 a0 = 0, a1 = 0, a2 = 0, a3 = 0;
#pragma unroll
        for (int k = 0; k < 8; k++) {
            ulonglong2 yv = yp[k];
            ulonglong2 c0 = w0[k], c1 = w1[k], c2 = w2[k], c3 = w3[k];
            a0 = ffma2(c0.x, yv.x, a0); a0 = ffma2(c0.y, yv.y, a0);
            a1 = ffma2(c1.x, yv.x, a1); a1 = ffma2(c1.y, yv.y, a1);
            a2 = ffma2(c2.x, yv.x, a2); a2 = ffma2(c2.y, yv.y, a2);
            a3 = ffma2(c3.x, yv.x, a3); a3 = ffma2(c3.y, yv.y, a3);
        }
        float l0 = hadd(a0) + s->wcb[0];
        float l1 = hadd(a1) + s->wcb[1];
        float l2 = hadd(a2) + s->wcb[2];
        float l3 = hadd(a3) + s->wcb[3];
        float m  = fmaxf(fmaxf(l0, l1), fmaxf(l2, l3));
        float e0 = __expf(l0 - m), e1 = __expf(l1 - m);
        float e2 = __expf(l2 - m), e3 = __expf(l3 - m);
        float rs = __fdividef(1.f, e0 + e1 + e2 + e3);
        float4 o = make_float4(e0 * rs, e1 * rs, e2 * rs, e3 * rs);
        reinterpret_cast<float4*>(out)[((size_t)(gbase + e)) * T_ + t] = o;
    }
}

extern "C" void kernel_launch(void* const* d_in, const int* in_sizes, int n_in,
                              void* d_out, int out_size)
{
    const float* x   = (const float*)d_in[0];
    const float* Wi1 = (const float*)d_in[1];
    const float* Wh1 = (const float*)d_in[2];
    const float* bi1 = (const float*)d_in[3];
    const float* bh1 = (const float*)d_in[4];
    const float* Wi5 = (const float*)d_in[5];
    const float* Wh5 = (const float*)d_in[6];
    const float* bi5 = (const float*)d_in[7];
    const float* bh5 = (const float*)d_in[8];
    const float* Wc  = (const float*)d_in[9];
    const float* bc  = (const float*)d_in[10];
    float* out = (float*)d_out;

    static bool once = []() {
        cudaFuncSetAttribute(fused_gru,
            cudaFuncAttributeMaxDynamicSharedMemorySize, (int)sizeof(Smem));
        return true;
    }();
    (void)once;

    fused_gru<<<(B_ + NB - 1) / NB, NTHR, sizeof(Smem)>>>(
        x, Wi1, Wh1, bi1, bh1, Wi5, Wh5, bi5, bh5, Wc, bc, out);
}